// round 6
// baseline (speedup 1.0000x reference)
#include <cuda_runtime.h>
#include <cuda_bf16.h>

// CenterLoss: loss = sum_i clamp(||pred_i - centers[target_i]||^2, 1e-12, 1e12)
//                    + BATCH*(NUM_CLASSES-1)*1e-12
//
// pred [16384,1024] f32, centers [10000,1024] f32, target [16384] i32.
// Output: scalar f32. Single fused kernel, deterministic reduction.
//
// R4: 128-thread CTAs with occ=8 -> 64-reg budget so the 16 front-batched
// float4 loads stay register-resident (true MLP~16/thread). Same 32 warps/SM.

#define BATCH       16384
#define NUM_CLASSES 10000
#define FEAT_DIM    1024

#define NWARPS      4
#define NTHREADS    (NWARPS * 32)      // 128
#define GRID        (BATCH / NWARPS)   // 4096 CTAs, one row per warp

__device__ float g_partial[GRID];
__device__ int   g_ticket = 0;   // self-resetting, starts 0 at module load

__global__ __launch_bounds__(NTHREADS, 8)   // 128*8 = 1024 thr/SM -> 64 regs/thread
void center_loss_fused(const float* __restrict__ pred,
                       const float* __restrict__ centers,
                       const int* __restrict__ target,
                       float* __restrict__ out)
{
    const int tid  = threadIdx.x;
    const int lane = tid & 31;
    const int wid  = tid >> 5;
    const int row  = blockIdx.x * NWARPS + wid;   // one row per warp

    int cls = target[row];
    cls = min(max(cls, 0), NUM_CLASSES - 1);      // never fault

    const float4* p4 = reinterpret_cast<const float4*>(pred    + (size_t)row * FEAT_DIM);
    const float4* c4 = reinterpret_cast<const float4*>(centers + (size_t)cls * FEAT_DIM);

    // 1024 floats / 32 lanes = 8 float4 per lane per operand.
    // Front-batch all 16 loads; with the 64-reg budget these stay live.
    float4 p[8], c[8];
    #pragma unroll
    for (int i = 0; i < 8; ++i) p[i] = __ldg(&p4[lane + i * 32]);
    #pragma unroll
    for (int i = 0; i < 8; ++i) c[i] = __ldg(&c4[lane + i * 32]);

    float s = 0.0f;
    #pragma unroll
    for (int i = 0; i < 8; ++i) {
        float dx = p[i].x - c[i].x;
        float dy = p[i].y - c[i].y;
        float dz = p[i].z - c[i].z;
        float dw = p[i].w - c[i].w;
        s = fmaf(dx, dx, s);
        s = fmaf(dy, dy, s);
        s = fmaf(dz, dz, s);
        s = fmaf(dw, dw, s);
    }

    // warp reduce
    #pragma unroll
    for (int off = 16; off > 0; off >>= 1)
        s += __shfl_xor_sync(0xFFFFFFFFu, s, off);

    // clamp per row
    s = fminf(fmaxf(s, 1e-12f), 1e12f);

    // combine the 4 warp-row sums of this CTA
    __shared__ float warp_sum[NWARPS];
    if (lane == 0) warp_sum[wid] = s;
    __syncthreads();

    __shared__ bool is_last;
    if (tid == 0) {
        float blocksum = (warp_sum[0] + warp_sum[1]) + (warp_sum[2] + warp_sum[3]);
        g_partial[blockIdx.x] = blocksum;
        __threadfence();
        int t = atomicAdd(&g_ticket, 1);
        is_last = (t == GRID - 1);
    }
    __syncthreads();

    // Last CTA: deterministic fixed-order reduction of all partials.
    if (is_last) {
        __threadfence();  // acquire: see all g_partial writes
        float v = 0.0f;
        #pragma unroll
        for (int i = 0; i < GRID / NTHREADS; ++i)   // 32 per thread, fixed order
            v += g_partial[tid + i * NTHREADS];

        #pragma unroll
        for (int off = 16; off > 0; off >>= 1)
            v += __shfl_xor_sync(0xFFFFFFFFu, v, off);

        __shared__ float red[NWARPS];
        if (lane == 0) red[wid] = v;
        __syncthreads();

        if (wid == 0) {
            float r = (lane < NWARPS) ? red[lane] : 0.0f;
            #pragma unroll
            for (int off = 2; off > 0; off >>= 1)
                r += __shfl_xor_sync(0xFFFFFFFFu, r, off);
            if (lane == 0) {
                const float masked_const =
                    (float)((double)BATCH * (double)(NUM_CLASSES - 1) * 1e-12);
                out[0] = r + masked_const;
                g_ticket = 0;   // reset for next graph replay
            }
        }
    }
}

extern "C" void kernel_launch(void* const* d_in, const int* in_sizes, int n_in,
                              void* d_out, int out_size)
{
    const float* pred    = (const float*)d_in[0];
    const float* centers = (const float*)d_in[1];
    const int*   target  = (const int*)d_in[2];
    float*       out     = (float*)d_out;

    center_loss_fused<<<GRID, NTHREADS>>>(pred, centers, target, out);
}

// round 7
// speedup vs baseline: 1.2320x; 1.2320x over previous
#include <cuda_runtime.h>
#include <cuda_bf16.h>

// CenterLoss: loss = sum_i clamp(||pred_i - centers[target_i]||^2, 1e-12, 1e12)
//                    + BATCH*(NUM_CLASSES-1)*1e-12
//
// pred [16384,1024] f32, centers [10000,1024] f32, target [16384] i32.
// Output: scalar f32.
//
// R7: R3's proven shape (256 thr/CTA, occ 8 -> ~56 warps/SM) but SINGLE-WAVE:
// 1024 CTAs all resident simultaneously, each warp handles 2 rows. Kills the
// 1.73-wave imbalance tail of R3.

#define BATCH        16384
#define NUM_CLASSES  10000
#define FEAT_DIM     1024

#define NWARPS        8
#define NTHREADS      (NWARPS * 32)           // 256
#define ROWS_PER_WARP 2
#define GRID          (BATCH / (NWARPS * ROWS_PER_WARP))   // 1024 CTAs — one wave

__device__ float g_partial[GRID];
__device__ int   g_ticket = 0;   // self-resetting

__global__ __launch_bounds__(NTHREADS, 8)
void center_loss_fused(const float* __restrict__ pred,
                       const float* __restrict__ centers,
                       const int* __restrict__ target,
                       float* __restrict__ out)
{
    const int tid  = threadIdx.x;
    const int lane = tid & 31;
    const int wid  = tid >> 5;

    float warp_total = 0.0f;

    #pragma unroll
    for (int j = 0; j < ROWS_PER_WARP; ++j) {
        const int row = (blockIdx.x * NWARPS + wid) * ROWS_PER_WARP + j;

        int cls = target[row];
        cls = min(max(cls, 0), NUM_CLASSES - 1);   // never fault

        const float4* p4 = reinterpret_cast<const float4*>(pred    + (size_t)row * FEAT_DIM);
        const float4* c4 = reinterpret_cast<const float4*>(centers + (size_t)cls * FEAT_DIM);

        float s = 0.0f;
        #pragma unroll
        for (int i = 0; i < 8; ++i) {
            float4 p = __ldg(&p4[lane + i * 32]);
            float4 c = __ldg(&c4[lane + i * 32]);
            float dx = p.x - c.x;
            float dy = p.y - c.y;
            float dz = p.z - c.z;
            float dw = p.w - c.w;
            s = fmaf(dx, dx, s);
            s = fmaf(dy, dy, s);
            s = fmaf(dz, dz, s);
            s = fmaf(dw, dw, s);
        }

        // warp reduce this row
        #pragma unroll
        for (int off = 16; off > 0; off >>= 1)
            s += __shfl_xor_sync(0xFFFFFFFFu, s, off);

        // per-row clamp, accumulate
        warp_total += fminf(fmaxf(s, 1e-12f), 1e12f);
    }

    // combine the 8 warp totals of this CTA
    __shared__ float warp_sum[NWARPS];
    if (lane == 0) warp_sum[wid] = warp_total;
    __syncthreads();

    __shared__ bool is_last;
    if (tid == 0) {
        float blocksum = 0.0f;
        #pragma unroll
        for (int i = 0; i < NWARPS; ++i) blocksum += warp_sum[i];
        g_partial[blockIdx.x] = blocksum;
        __threadfence();
        int t = atomicAdd(&g_ticket, 1);
        is_last = (t == GRID - 1);
    }
    __syncthreads();

    // Last CTA: deterministic fixed-order reduction of all 1024 partials.
    if (is_last) {
        __threadfence();  // acquire: see all g_partial writes
        float v = 0.0f;
        #pragma unroll
        for (int i = 0; i < GRID / NTHREADS; ++i)   // 4 per thread, fixed order
            v += g_partial[tid + i * NTHREADS];

        #pragma unroll
        for (int off = 16; off > 0; off >>= 1)
            v += __shfl_xor_sync(0xFFFFFFFFu, v, off);

        __shared__ float red[NWARPS];
        if (lane == 0) red[wid] = v;
        __syncthreads();

        if (wid == 0) {
            float r = (lane < NWARPS) ? red[lane] : 0.0f;
            #pragma unroll
            for (int off = 4; off > 0; off >>= 1)
                r += __shfl_xor_sync(0xFFFFFFFFu, r, off);
            if (lane == 0) {
                const float masked_const =
                    (float)((double)BATCH * (double)(NUM_CLASSES - 1) * 1e-12);
                out[0] = r + masked_const;
                g_ticket = 0;   // reset for next graph replay
            }
        }
    }
}

extern "C" void kernel_launch(void* const* d_in, const int* in_sizes, int n_in,
                              void* d_out, int out_size)
{
    const float* pred    = (const float*)d_in[0];
    const float* centers = (const float*)d_in[1];
    const int*   target  = (const int*)d_in[2];
    float*       out     = (float*)d_out;

    center_loss_fused<<<GRID, NTHREADS>>>(pred, centers, target, out);
}